// round 2
// baseline (speedup 1.0000x reference)
#include <cuda_runtime.h>
#include <cuda_bf16.h>

// ---------------- problem constants ----------------
#define HN    256
#define BB    64
#define NN    4096
#define TT    100
#define GBLK  32

#define V_REST_C   (-70.0f)
#define V_RESET_C  (-75.0f)
#define V_THRESH_C (-55.0f)

// ---------------- static device scratch (no allocations allowed) ----------------
__device__ float d_gA[4 * BB * NN];        // k-split partials of spikes@adj (4 MB)
__device__ float d_g[BB * NN];             // g = spikes@adj               (1 MB)
__device__ float d_x0p[8 * BB * HN];       // k-split partials of g@W0
__device__ float d_x0[BB * HN];            // x0_pre = g@W0 + b0
__device__ float d_sp0[BB * HN];
__device__ float d_sp1[BB * HN];
__device__ float d_x1[BB * HN];
__device__ float d_x2[BB * HN];
__device__ unsigned d_barcount;            // zero-init; self-resetting
__device__ unsigned d_bargen;              // monotonic epoch (replay-safe)

// ---------------- LIF micro-step (matches reference expression order) ----------------
__device__ __forceinline__ void lif_step(float& v, float& isyn, float& refr,
                                         float ib, float& sp) {
    const bool  in_refr = refr > 0.0f;
    const float isyn_u  = isyn + (ib - isyn * 0.2f);               // i + (-i/5 + ib)*1
    const float v_u     = v + (isyn_u - (v - V_REST_C)) * 0.05f;   // v + (-(v-vr)+i_u)/20
    const bool  spike   = (!in_refr) && (v_u >= V_THRESH_C);
    v    = in_refr ? v    : (spike ? V_RESET_C : v_u);
    isyn = in_refr ? isyn : isyn_u;
    refr = in_refr ? (refr - 1.0f) : (spike ? 2.0f : refr);
    sp   = spike ? 1.0f : 0.0f;
}

// ---------------- grid barrier: sense-reversing, monotonic epoch ----------------
__device__ __forceinline__ void gbar() {
    __syncthreads();
    if (threadIdx.x == 0) {
        __threadfence();                                   // release my block's writes
        unsigned gen = *((volatile unsigned*)&d_bargen);   // read epoch BEFORE arriving
        if (atomicAdd(&d_barcount, 1u) == GBLK - 1u) {
            d_barcount = 0u;
            __threadfence();
            atomicAdd(&d_bargen, 1u);                      // release
        } else {
            while (*((volatile unsigned*)&d_bargen) == gen) { }
        }
        __threadfence();                                   // acquire
    }
    __syncthreads();
}

// ---------------- setup SGEMM: Cpart[gy] = A[64,Kchunk]@B[Kchunk,N] ----------------
// BM=64, BN=32, BK=32; 256 threads (16x16, TM=4, TN=2). grid=(N/32, ksplit)
__global__ void __launch_bounds__(256) k_sgemm_part(
    const float* __restrict__ A, const float* __restrict__ B,
    float* __restrict__ Cp, int lda, int Kchunk, int N)
{
    __shared__ float As[32][64];
    __shared__ float Bs[32][32];
    const int tid = threadIdx.x;
    const int n0  = blockIdx.x * 32;
    const int k0  = blockIdx.y * Kchunk;
    const int ty2 = tid >> 4;      // 0..15 -> 4 rows
    const int tx2 = tid & 15;      // 0..15 -> 2 cols

    float acc[4][2];
#pragma unroll
    for (int i = 0; i < 4; i++) { acc[i][0] = 0.f; acc[i][1] = 0.f; }

    const int ra = tid >> 3;              // 0..31
    const int kq = (tid & 7) << 2;        // 0..28
    for (int kt = 0; kt < Kchunk; kt += 32) {
#pragma unroll
        for (int p = 0; p < 2; ++p) {
            const int r = ra + 32 * p;
            float4 av = *(const float4*)(A + (size_t)r * lda + (k0 + kt + kq));
            As[kq + 0][r] = av.x;
            As[kq + 1][r] = av.y;
            As[kq + 2][r] = av.z;
            As[kq + 3][r] = av.w;
        }
        {
            float4 bv = *(const float4*)(B + (size_t)(k0 + kt + ra) * N + (n0 + kq));
            *(float4*)&Bs[ra][kq] = bv;
        }
        __syncthreads();
#pragma unroll
        for (int kk = 0; kk < 32; ++kk) {
            float4 a = *(const float4*)&As[kk][ty2 * 4];
            float2 b = *(const float2*)&Bs[kk][tx2 * 2];
            acc[0][0] += a.x * b.x;  acc[0][1] += a.x * b.y;
            acc[1][0] += a.y * b.x;  acc[1][1] += a.y * b.y;
            acc[2][0] += a.z * b.x;  acc[2][1] += a.z * b.y;
            acc[3][0] += a.w * b.x;  acc[3][1] += a.w * b.y;
        }
        __syncthreads();
    }
    float* C = Cp + (size_t)blockIdx.y * (64 * (size_t)N);
#pragma unroll
    for (int i = 0; i < 4; ++i) {
#pragma unroll
        for (int j = 0; j < 2; ++j)
            C[(size_t)(ty2 * 4 + i) * N + n0 + tx2 * 2 + j] = acc[i][j];
    }
}

// g = sum of 4 partials
__global__ void __launch_bounds__(256) k_reduce_g() {
    int i = blockIdx.x * blockDim.x + threadIdx.x;
    int stride = gridDim.x * blockDim.x;
    for (; i < BB * NN; i += stride)
        d_g[i] = (d_gA[i] + d_gA[BB * NN + i]) +
                 (d_gA[2 * BB * NN + i] + d_gA[3 * BB * NN + i]);
}

// x0 = sum of 8 partials + b0
__global__ void __launch_bounds__(256) k_reduce_x0(const float* __restrict__ b0) {
    int i = blockIdx.x * 256 + threadIdx.x;   // 64 blocks x 256 = 16384
    float s = 0.f;
#pragma unroll
    for (int p = 0; p < 8; ++p) s += d_x0p[p * (BB * HN) + i];
    d_x0[i] = s + b0[i & 255];
}

// ---------------- pieces of the persistent kernel ----------------
__device__ __forceinline__ int stage_to_smem(const float* __restrict__ src,
                                             float* __restrict__ s_x, int tid) {
    // copy 64x256 floats gmem->smem via L2 (__ldcg), return per-thread nonzero flag
    const float4* s4 = (const float4*)src;
    float4* dd = (float4*)s_x;
    int flag = 0;
#pragma unroll
    for (int it = 0; it < 16; ++it) {
        int i = tid + it * 256;
        float4 v = __ldcg(s4 + i);
        flag |= (v.x != 0.f) | (v.y != 0.f) | (v.z != 0.f) | (v.w != 0.f);
        dd[i] = v;
    }
    return flag;
}

// GEMM phase: xout[64,256] = sp[64,256] @ W[256,256] + bias ; each block: 2 rows
__device__ __forceinline__ void gemm_phase(const float* __restrict__ sp,
                                           const float* __restrict__ W,
                                           const float* __restrict__ bias,
                                           float* __restrict__ xout,
                                           int bid, int tid,
                                           float* s_rows, float* s_psum) {
    int flag = 0;
#pragma unroll
    for (int it = 0; it < 2; ++it) {
        int i = tid + it * 256;
        float v = __ldcg(sp + bid * 512 + i);
        flag |= (v != 0.f);
        s_rows[i] = v;
    }
    const int tx = tid & 63;
    const int ty = tid >> 6;
    const int c0 = tx * 4;
    const int kb = ty * 64;
    const int any = __syncthreads_or(flag);

    if (any) {   // general path
        float4 a0 = {0.f, 0.f, 0.f, 0.f}, a1 = {0.f, 0.f, 0.f, 0.f};
        const float* s0 = s_rows + kb;
        const float* s1 = s_rows + 256 + kb;
#pragma unroll 8
        for (int k = 0; k < 64; ++k) {
            float4 w = __ldg((const float4*)(W + (size_t)(kb + k) * 256 + c0));
            float u0 = s0[k], u1 = s1[k];
            a0.x += u0 * w.x; a0.y += u0 * w.y; a0.z += u0 * w.z; a0.w += u0 * w.w;
            a1.x += u1 * w.x; a1.y += u1 * w.y; a1.z += u1 * w.z; a1.w += u1 * w.w;
        }
        *(float4*)&s_psum[(ty * 2 + 0) * 256 + c0] = a0;
        *(float4*)&s_psum[(ty * 2 + 1) * 256 + c0] = a1;
        __syncthreads();
        if (ty == 0) {
#pragma unroll
            for (int r = 0; r < 2; ++r) {
                float4 p0 = *(float4*)&s_psum[(0 + r) * 256 + c0];
                float4 p1 = *(float4*)&s_psum[(2 + r) * 256 + c0];
                float4 p2 = *(float4*)&s_psum[(4 + r) * 256 + c0];
                float4 p3 = *(float4*)&s_psum[(6 + r) * 256 + c0];
                float4 bb = __ldg((const float4*)(bias + c0));
                float4 o;
                o.x = ((p0.x + p1.x) + (p2.x + p3.x)) + bb.x;
                o.y = ((p0.y + p1.y) + (p2.y + p3.y)) + bb.y;
                o.z = ((p0.z + p1.z) + (p2.z + p3.z)) + bb.z;
                o.w = ((p0.w + p1.w) + (p2.w + p3.w)) + bb.w;
                *(float4*)(xout + (size_t)(bid * 2 + r) * 256 + c0) = o;
            }
        }
        __syncthreads();
    } else {     // all-zero input: output == bias exactly (0*w sums to +0, +bias)
        if (ty == 0) {
            float4 bb = __ldg((const float4*)(bias + c0));
#pragma unroll
            for (int r = 0; r < 2; ++r)
                *(float4*)(xout + (size_t)(bid * 2 + r) * 256 + c0) = bb;
        }
        __syncthreads();
    }
}

// LIF scan for hidden layers 1/2 with exact fixed-point fast path
__device__ __forceinline__ void lif_scan_layer(const float* __restrict__ xin,
                                               float* __restrict__ spout,
                                               float& v, float& isyn, float& refr,
                                               int tid, float* s_x) {
    int flag = stage_to_smem(xin, s_x, tid);
    flag |= (v != V_REST_C) | (isyn != 0.f) | (refr != 0.f);
    const int any = __syncthreads_or(flag);
    if (any) {
        float nxt = s_x[tid];
#pragma unroll 4
        for (int b = 0; b < 64; ++b) {
            float ib = nxt;
            if (b < 63) nxt = s_x[(b + 1) * 256 + tid];
            float sp;
            lif_step(v, isyn, refr, ib, sp);
            spout[b * 256 + tid] = sp;
        }
    } else {
        // exact stationary point: every step yields spike=0, state unchanged
        float4 z = {0.f, 0.f, 0.f, 0.f};
        float4* o4 = (float4*)spout;
#pragma unroll
        for (int it = 0; it < 16; ++it) o4[tid + it * 256] = z;
    }
    __syncthreads();
}

// ---------------- persistent time-loop kernel ----------------
__global__ void __launch_bounds__(256) k_persist(
    const float* __restrict__ x0pre,
    const float* __restrict__ W1, const float* __restrict__ b1,
    const float* __restrict__ W2, const float* __restrict__ b2,
    float* __restrict__ traces)
{
    extern __shared__ float sh[];
    float* s_x    = sh;                 // 16384 floats (64 KB)
    float* s_rows = sh + 16384;         // 512 floats
    float* s_psum = sh + 16896;         // 2048 floats
    const int tid = threadIdx.x;
    const int bid = blockIdx.x;

    float v0 = V_REST_C, i0 = 0.f, r0 = 0.f;
    float v1 = V_REST_C, i1 = 0.f, r1 = 0.f;
    float v2 = V_REST_C, i2 = 0.f, r2 = 0.f;

    for (int t = 0; t < TT; ++t) {
        // ---- LIF layer 0 (block 0; x0pre constant, L1-cached) ----
        if (bid == 0) {
            float nxt = __ldg(x0pre + tid);
#pragma unroll 4
            for (int b = 0; b < 64; ++b) {
                float ib = nxt;
                if (b < 63) nxt = __ldg(x0pre + (b + 1) * 256 + tid);
                float sp;
                lif_step(v0, i0, r0, ib, sp);
                d_sp0[b * 256 + tid] = sp;
            }
        }
        gbar();
        // ---- x1 = sp0 @ W1 + b1 (all blocks) ----
        gemm_phase(d_sp0, W1, b1, d_x1, bid, tid, s_rows, s_psum);
        gbar();
        // ---- LIF layer 1 (block 0) ----
        if (bid == 0) lif_scan_layer(d_x1, d_sp1, v1, i1, r1, tid, s_x);
        gbar();
        // ---- x2 = sp1 @ W2 + b2 (all blocks) ----
        gemm_phase(d_sp1, W2, b2, d_x2, bid, tid, s_rows, s_psum);
        gbar();
        // ---- LIF layer 2 (block 0) -> traces[t] ----
        if (bid == 0) lif_scan_layer(d_x2, traces + (size_t)t * (BB * HN),
                                     v2, i2, r2, tid, s_x);
        // next iteration's first barrier orders traces/sp writes vs readers
    }
}

// ---------------- hidden reduction + policy logits ----------------
// logits[b][o] = (sum_t traces[t][b][:]/T) @ Wp[:,o] + bp[o]
__global__ void __launch_bounds__(256) k_logits(const float* __restrict__ traces,
                                                const float* __restrict__ Wp,
                                                const float* __restrict__ bp,
                                                float* __restrict__ out)
{
    __shared__ float hrow[HN];
    const int b = blockIdx.x;
    const int tid = threadIdx.x;
    float s = 0.f;
    for (int t = 0; t < TT; ++t)
        s += traces[(size_t)t * (BB * HN) + b * HN + tid];
    hrow[tid] = __fdiv_rn(s, 100.0f);
    __syncthreads();
    if (tid < 5) {
        float acc = 0.f;
        for (int h = 0; h < HN; ++h)
            acc += hrow[h] * __ldg(Wp + h * 5 + tid);
        out[b * 5 + tid] = acc + __ldg(bp + tid);
    }
}

// ---------------- launch ----------------
extern "C" void kernel_launch(void* const* d_in, const int* in_sizes, int n_in,
                              void* d_out, int out_size) {
    const float* spikes = (const float*)d_in[0];
    const float* adj    = (const float*)d_in[1];
    const float* W0     = (const float*)d_in[2];
    const float* b0     = (const float*)d_in[3];
    const float* W1     = (const float*)d_in[4];
    const float* b1     = (const float*)d_in[5];
    const float* W2     = (const float*)d_in[6];
    const float* b2     = (const float*)d_in[7];
    const float* Wp     = (const float*)d_in[8];
    const float* bp     = (const float*)d_in[9];
    float* out = (float*)d_out;        // [logits(64*5) | traces(100*64*256)]
    float* traces = out + BB * 5;

    const int smem_bytes = (16384 + 512 + 2048) * (int)sizeof(float);
    cudaFuncSetAttribute(k_persist, cudaFuncAttributeMaxDynamicSharedMemorySize,
                         smem_bytes);

    float* gA  = nullptr; cudaGetSymbolAddress((void**)&gA,  d_gA);
    float* g   = nullptr; cudaGetSymbolAddress((void**)&g,   d_g);
    float* x0p = nullptr; cudaGetSymbolAddress((void**)&x0p, d_x0p);
    float* x0  = nullptr; cudaGetSymbolAddress((void**)&x0,  d_x0);

    // g = spikes @ adj   (K=4096 split 4)
    k_sgemm_part<<<dim3(NN / 32, 4), 256>>>(spikes, adj, gA, NN, NN / 4, NN);
    k_reduce_g<<<256, 256>>>();
    // x0 = g @ W0 + b0   (K=4096 split 8)
    k_sgemm_part<<<dim3(HN / 32, 8), 256>>>(g, W0, x0p, NN, NN / 8, HN);
    k_reduce_x0<<<64, 256>>>(b0);
    // 100-step recurrent loop (persistent, 32 co-resident blocks)
    k_persist<<<GBLK, 256, smem_bytes>>>(x0, W1, b1, W2, b2, traces);
    // hidden reduction + policy head
    k_logits<<<BB, 256>>>(traces, Wp, bp, out);
}

// round 3
// speedup vs baseline: 10.4143x; 10.4143x over previous
#include <cuda_runtime.h>
#include <cuda_bf16.h>

// ---------------- problem constants ----------------
#define HN    256
#define BB    64
#define NN    4096
#define TT    100
#define GBLK  32

#define V_REST_C   (-70.0f)
#define V_RESET_C  (-75.0f)
#define V_THRESH_C (-55.0f)

// ---------------- static device scratch (no allocations allowed) ----------------
__device__ float d_gA[4 * BB * NN];        // k-split partials of spikes@adj (4 MB)
__device__ float d_g[BB * NN];             // g = spikes@adj               (1 MB)
__device__ float d_x0p[8 * BB * HN];       // k-split partials of g@W0
__device__ float d_x0[BB * HN];            // x0_pre = g@W0 + b0
__device__ float d_sp0[BB * HN];
__device__ float d_sp1[BB * HN];
__device__ float d_x1[BB * HN];
__device__ float d_x2[BB * HN];
__device__ unsigned d_barcount;            // zero-init; self-resetting
__device__ unsigned d_bargen;              // monotonic epoch (replay-safe)
__device__ unsigned d_need_slow;           // set by k_spec; reset by k_init

// ---------------- LIF micro-step (matches reference expression order) ----------------
__device__ __forceinline__ void lif_step(float& v, float& isyn, float& refr,
                                         float ib, float& sp) {
    const bool  in_refr = refr > 0.0f;
    const float isyn_u  = isyn + (ib - isyn * 0.2f);               // i + (-i/5 + ib)*1
    const float v_u     = v + (isyn_u - (v - V_REST_C)) * 0.05f;   // v + (-(v-vr)+i_u)/20
    const bool  spike   = (!in_refr) && (v_u >= V_THRESH_C);
    v    = in_refr ? v    : (spike ? V_RESET_C : v_u);
    isyn = in_refr ? isyn : isyn_u;
    refr = in_refr ? (refr - 1.0f) : (spike ? 2.0f : refr);
    sp   = spike ? 1.0f : 0.0f;
}

// ---------------- grid barrier: sense-reversing, monotonic epoch ----------------
__device__ __forceinline__ void gbar() {
    __syncthreads();
    if (threadIdx.x == 0) {
        __threadfence();
        unsigned gen = *((volatile unsigned*)&d_bargen);
        if (atomicAdd(&d_barcount, 1u) == GBLK - 1u) {
            d_barcount = 0u;
            __threadfence();
            atomicAdd(&d_bargen, 1u);
        } else {
            while (*((volatile unsigned*)&d_bargen) == gen) { }
        }
        __threadfence();
    }
    __syncthreads();
}

// ---------------- per-replay init ----------------
__global__ void k_init() {
    if (threadIdx.x == 0) d_need_slow = 0u;
}

// ---------------- setup SGEMM: Cpart[gy] = A[64,Kchunk]@B[Kchunk,N] ----------------
// BM=64, BN=32, BK=32; 256 threads (16x16, TM=4, TN=2). grid=(N/32, ksplit)
__global__ void __launch_bounds__(256) k_sgemm_part(
    const float* __restrict__ A, const float* __restrict__ B,
    float* __restrict__ Cp, int lda, int Kchunk, int N)
{
    __shared__ float As[32][64];
    __shared__ float Bs[32][32];
    const int tid = threadIdx.x;
    const int n0  = blockIdx.x * 32;
    const int k0  = blockIdx.y * Kchunk;
    const int ty2 = tid >> 4;
    const int tx2 = tid & 15;

    float acc[4][2];
#pragma unroll
    for (int i = 0; i < 4; i++) { acc[i][0] = 0.f; acc[i][1] = 0.f; }

    const int ra = tid >> 3;
    const int kq = (tid & 7) << 2;
    for (int kt = 0; kt < Kchunk; kt += 32) {
#pragma unroll
        for (int p = 0; p < 2; ++p) {
            const int r = ra + 32 * p;
            float4 av = *(const float4*)(A + (size_t)r * lda + (k0 + kt + kq));
            As[kq + 0][r] = av.x;
            As[kq + 1][r] = av.y;
            As[kq + 2][r] = av.z;
            As[kq + 3][r] = av.w;
        }
        {
            float4 bv = *(const float4*)(B + (size_t)(k0 + kt + ra) * N + (n0 + kq));
            *(float4*)&Bs[ra][kq] = bv;
        }
        __syncthreads();
#pragma unroll
        for (int kk = 0; kk < 32; ++kk) {
            float4 a = *(const float4*)&As[kk][ty2 * 4];
            float2 b = *(const float2*)&Bs[kk][tx2 * 2];
            acc[0][0] += a.x * b.x;  acc[0][1] += a.x * b.y;
            acc[1][0] += a.y * b.x;  acc[1][1] += a.y * b.y;
            acc[2][0] += a.z * b.x;  acc[2][1] += a.z * b.y;
            acc[3][0] += a.w * b.x;  acc[3][1] += a.w * b.y;
        }
        __syncthreads();
    }
    float* C = Cp + (size_t)blockIdx.y * (64 * (size_t)N);
#pragma unroll
    for (int i = 0; i < 4; ++i) {
#pragma unroll
        for (int j = 0; j < 2; ++j)
            C[(size_t)(ty2 * 4 + i) * N + n0 + tx2 * 2 + j] = acc[i][j];
    }
}

__global__ void __launch_bounds__(256) k_reduce_g() {
    int i = blockIdx.x * blockDim.x + threadIdx.x;
    int stride = gridDim.x * blockDim.x;
    for (; i < BB * NN; i += stride)
        d_g[i] = (d_gA[i] + d_gA[BB * NN + i]) +
                 (d_gA[2 * BB * NN + i] + d_gA[3 * BB * NN + i]);
}

__global__ void __launch_bounds__(256) k_reduce_x0(const float* __restrict__ b0) {
    int i = blockIdx.x * 256 + threadIdx.x;
    float s = 0.f;
#pragma unroll
    for (int p = 0; p < 8; ++p) s += d_x0p[p * (BB * HN) + i];
    d_x0[i] = s + b0[i & 255];
}

// ---------------- zero-fill traces (output region) ----------------
__global__ void __launch_bounds__(256) k_zero_traces(float* __restrict__ traces) {
    const float4 z = {0.f, 0.f, 0.f, 0.f};
    float4* t4 = (float4*)traces;
    int i = blockIdx.x * blockDim.x + threadIdx.x;
    int stride = gridDim.x * blockDim.x;
    const int n4 = (TT * BB * HN) / 4;
    for (; i < n4; i += stride) t4[i] = z;
}

// ---------------- speculative linear-mode LIF scan ----------------
// In the no-spike, non-refractory regime (validated a posteriori), the LIF
// dynamics are linear:  with w = 0.05*i_syn - 3.5:
//   w' = fma(w, 0.8, m_b),  v' = fma(v, 0.95, w'),  m_b = 0.05*i_b - 0.7
// Layer0 input cycles over x0_pre[b][n] (period 64); layers 1/2 see constant
// input b1[n]/b2[n] (since upstream spikes are all zero under the same
// speculation). If any v ever reaches within 0.01 of threshold, we flag the
// exact slow path. 24 blocks x 32 threads: block i -> layer i/8, 32 neurons.
__global__ void __launch_bounds__(32) k_spec(const float* __restrict__ x0,
                                             const float* __restrict__ b1,
                                             const float* __restrict__ b2)
{
    const int layer = blockIdx.x >> 3;
    const int n = ((blockIdx.x & 7) << 5) + threadIdx.x;
    float v = V_REST_C, w = -3.5f, vmax = -1e30f;

    if (layer == 0) {
        float m[64];
#pragma unroll
        for (int b = 0; b < 64; ++b)
            m[b] = __fmaf_rn(__ldg(x0 + b * HN + n), 0.05f, -0.7f);
        for (int t = 0; t < TT; ++t) {
#pragma unroll
            for (int b = 0; b < 64; ++b) {
                w = __fmaf_rn(w, 0.8f, m[b]);
                v = __fmaf_rn(v, 0.95f, w);
                vmax = fmaxf(vmax, v);
            }
        }
    } else {
        const float* bb = (layer == 1) ? b1 : b2;
        const float m = __fmaf_rn(__ldg(bb + n), 0.05f, -0.7f);
        for (int t = 0; t < TT; ++t) {
#pragma unroll
            for (int b = 0; b < 64; ++b) {
                w = __fmaf_rn(w, 0.8f, m);
                v = __fmaf_rn(v, 0.95f, w);
                vmax = fmaxf(vmax, v);
            }
        }
    }
    unsigned bad = __ballot_sync(0xffffffffu, vmax >= (V_THRESH_C - 0.01f));
    if (threadIdx.x == 0 && bad) atomicOr(&d_need_slow, 1u);
}

// ---------------- exact fallback (round-2 verified path) ----------------
__device__ __forceinline__ int stage_to_smem(const float* __restrict__ src,
                                             float* __restrict__ s_x, int tid) {
    const float4* s4 = (const float4*)src;
    float4* dd = (float4*)s_x;
    int flag = 0;
#pragma unroll
    for (int it = 0; it < 16; ++it) {
        int i = tid + it * 256;
        float4 v = __ldcg(s4 + i);
        flag |= (v.x != 0.f) | (v.y != 0.f) | (v.z != 0.f) | (v.w != 0.f);
        dd[i] = v;
    }
    return flag;
}

__device__ __forceinline__ void gemm_phase(const float* __restrict__ sp,
                                           const float* __restrict__ W,
                                           const float* __restrict__ bias,
                                           float* __restrict__ xout,
                                           int bid, int tid,
                                           float* s_rows, float* s_psum) {
    int flag = 0;
#pragma unroll
    for (int it = 0; it < 2; ++it) {
        int i = tid + it * 256;
        float v = __ldcg(sp + bid * 512 + i);
        flag |= (v != 0.f);
        s_rows[i] = v;
    }
    const int tx = tid & 63;
    const int ty = tid >> 6;
    const int c0 = tx * 4;
    const int kb = ty * 64;
    const int any = __syncthreads_or(flag);

    if (any) {
        float4 a0 = {0.f, 0.f, 0.f, 0.f}, a1 = {0.f, 0.f, 0.f, 0.f};
        const float* s0 = s_rows + kb;
        const float* s1 = s_rows + 256 + kb;
#pragma unroll 8
        for (int k = 0; k < 64; ++k) {
            float4 ww = __ldg((const float4*)(W + (size_t)(kb + k) * 256 + c0));
            float u0 = s0[k], u1 = s1[k];
            a0.x += u0 * ww.x; a0.y += u0 * ww.y; a0.z += u0 * ww.z; a0.w += u0 * ww.w;
            a1.x += u1 * ww.x; a1.y += u1 * ww.y; a1.z += u1 * ww.z; a1.w += u1 * ww.w;
        }
        *(float4*)&s_psum[(ty * 2 + 0) * 256 + c0] = a0;
        *(float4*)&s_psum[(ty * 2 + 1) * 256 + c0] = a1;
        __syncthreads();
        if (ty == 0) {
#pragma unroll
            for (int r = 0; r < 2; ++r) {
                float4 p0 = *(float4*)&s_psum[(0 + r) * 256 + c0];
                float4 p1 = *(float4*)&s_psum[(2 + r) * 256 + c0];
                float4 p2 = *(float4*)&s_psum[(4 + r) * 256 + c0];
                float4 p3 = *(float4*)&s_psum[(6 + r) * 256 + c0];
                float4 bbv = __ldg((const float4*)(bias + c0));
                float4 o;
                o.x = ((p0.x + p1.x) + (p2.x + p3.x)) + bbv.x;
                o.y = ((p0.y + p1.y) + (p2.y + p3.y)) + bbv.y;
                o.z = ((p0.z + p1.z) + (p2.z + p3.z)) + bbv.z;
                o.w = ((p0.w + p1.w) + (p2.w + p3.w)) + bbv.w;
                *(float4*)(xout + (size_t)(bid * 2 + r) * 256 + c0) = o;
            }
        }
        __syncthreads();
    } else {
        if (ty == 0) {
            float4 bbv = __ldg((const float4*)(bias + c0));
#pragma unroll
            for (int r = 0; r < 2; ++r)
                *(float4*)(xout + (size_t)(bid * 2 + r) * 256 + c0) = bbv;
        }
        __syncthreads();
    }
}

__device__ __forceinline__ void lif_scan_layer(const float* __restrict__ xin,
                                               float* __restrict__ spout,
                                               float& v, float& isyn, float& refr,
                                               int tid, float* s_x) {
    int flag = stage_to_smem(xin, s_x, tid);
    flag |= (v != V_REST_C) | (isyn != 0.f) | (refr != 0.f);
    const int any = __syncthreads_or(flag);
    if (any) {
        float nxt = s_x[tid];
#pragma unroll 4
        for (int b = 0; b < 64; ++b) {
            float ib = nxt;
            if (b < 63) nxt = s_x[(b + 1) * 256 + tid];
            float sp;
            lif_step(v, isyn, refr, ib, sp);
            spout[b * 256 + tid] = sp;
        }
    } else {
        float4 z = {0.f, 0.f, 0.f, 0.f};
        float4* o4 = (float4*)spout;
#pragma unroll
        for (int it = 0; it < 16; ++it) o4[tid + it * 256] = z;
    }
    __syncthreads();
}

__global__ void __launch_bounds__(256) k_persist_slow(
    const float* __restrict__ x0pre,
    const float* __restrict__ W1, const float* __restrict__ b1,
    const float* __restrict__ W2, const float* __restrict__ b2,
    float* __restrict__ traces)
{
    // early-exit when speculation succeeded (coherent atomic read)
    if (atomicOr(&d_need_slow, 0u) == 0u) return;

    extern __shared__ float sh[];
    float* s_x    = sh;
    float* s_rows = sh + 16384;
    float* s_psum = sh + 16896;
    const int tid = threadIdx.x;
    const int bid = blockIdx.x;

    float v0 = V_REST_C, i0 = 0.f, r0 = 0.f;
    float v1 = V_REST_C, i1 = 0.f, r1 = 0.f;
    float v2 = V_REST_C, i2 = 0.f, r2 = 0.f;

    for (int t = 0; t < TT; ++t) {
        if (bid == 0) {
            float nxt = __ldg(x0pre + tid);
#pragma unroll 4
            for (int b = 0; b < 64; ++b) {
                float ib = nxt;
                if (b < 63) nxt = __ldg(x0pre + (b + 1) * 256 + tid);
                float sp;
                lif_step(v0, i0, r0, ib, sp);
                d_sp0[b * 256 + tid] = sp;
            }
        }
        gbar();
        gemm_phase(d_sp0, W1, b1, d_x1, bid, tid, s_rows, s_psum);
        gbar();
        if (bid == 0) lif_scan_layer(d_x1, d_sp1, v1, i1, r1, tid, s_x);
        gbar();
        gemm_phase(d_sp1, W2, b2, d_x2, bid, tid, s_rows, s_psum);
        gbar();
        if (bid == 0) lif_scan_layer(d_x2, traces + (size_t)t * (BB * HN),
                                     v2, i2, r2, tid, s_x);
    }
}

// ---------------- hidden reduction + policy logits ----------------
__global__ void __launch_bounds__(256) k_logits(const float* __restrict__ traces,
                                                const float* __restrict__ Wp,
                                                const float* __restrict__ bp,
                                                float* __restrict__ out)
{
    __shared__ float hrow[HN];
    const int b = blockIdx.x;
    const int tid = threadIdx.x;
    float s = 0.f;
    for (int t = 0; t < TT; ++t)
        s += traces[(size_t)t * (BB * HN) + b * HN + tid];
    hrow[tid] = __fdiv_rn(s, 100.0f);
    __syncthreads();
    if (tid < 5) {
        float acc = 0.f;
        for (int h = 0; h < HN; ++h)
            acc += hrow[h] * __ldg(Wp + h * 5 + tid);
        out[b * 5 + tid] = acc + __ldg(bp + tid);
    }
}

// ---------------- launch ----------------
extern "C" void kernel_launch(void* const* d_in, const int* in_sizes, int n_in,
                              void* d_out, int out_size) {
    const float* spikes = (const float*)d_in[0];
    const float* adj    = (const float*)d_in[1];
    const float* W0     = (const float*)d_in[2];
    const float* b0     = (const float*)d_in[3];
    const float* W1     = (const float*)d_in[4];
    const float* b1     = (const float*)d_in[5];
    const float* W2     = (const float*)d_in[6];
    const float* b2     = (const float*)d_in[7];
    const float* Wp     = (const float*)d_in[8];
    const float* bp     = (const float*)d_in[9];
    float* out = (float*)d_out;        // [logits(64*5) | traces(100*64*256)]
    float* traces = out + BB * 5;

    const int smem_bytes = (16384 + 512 + 2048) * (int)sizeof(float);
    cudaFuncSetAttribute(k_persist_slow, cudaFuncAttributeMaxDynamicSharedMemorySize,
                         smem_bytes);

    float* gA  = nullptr; cudaGetSymbolAddress((void**)&gA,  d_gA);
    float* g   = nullptr; cudaGetSymbolAddress((void**)&g,   d_g);
    float* x0p = nullptr; cudaGetSymbolAddress((void**)&x0p, d_x0p);
    float* x0  = nullptr; cudaGetSymbolAddress((void**)&x0,  d_x0);

    k_init<<<1, 32>>>();
    // g = spikes @ adj   (K=4096 split 4)
    k_sgemm_part<<<dim3(NN / 32, 4), 256>>>(spikes, adj, gA, NN, NN / 4, NN);
    k_reduce_g<<<256, 256>>>();
    // x0 = g @ W0 + b0   (K=4096 split 8)
    k_sgemm_part<<<dim3(HN / 32, 8), 256>>>(g, W0, x0p, NN, NN / 8, HN);
    k_reduce_x0<<<64, 256>>>(b0);
    // zero traces, then speculative linear-mode scan of all 3 layers
    k_zero_traces<<<400, 256>>>(traces);
    k_spec<<<24, 32>>>(x0, b1, b2);
    // exact fallback (early-exits when speculation validated)
    k_persist_slow<<<GBLK, 256, smem_bytes>>>(x0, W1, b1, W2, b2, traces);
    // hidden reduction + policy head
    k_logits<<<BB, 256>>>(traces, Wp, bp, out);
}